// round 7
// baseline (speedup 1.0000x reference)
#include <cuda_runtime.h>
#include <cstdint>

#define NB 16
#define HH 224
#define WW 224
#define GX 7
#define GYT 56               // 224/4 h-tiles
#define NBLK (GX*GYT*NB)     // 6272
#define NELEM 25690112       // 16*32*224*224

// 3 balanced base-128 digit planes of round(x * 2^18), NHWC s8 (32B per position)
__device__ __align__(16) signed char g_d1[NELEM];
__device__ __align__(16) signed char g_d2[NELEM];
__device__ __align__(16) signed char g_d3[NELEM];
__device__ double g_part[NBLK * 64];
__device__ float  g_scale[32];
__device__ float  g_bias[32];

__device__ __forceinline__ uint32_t smem_u32(const void* p) {
    uint32_t a;
    asm("{ .reg .u64 t; cvta.to.shared.u64 t, %1; cvt.u32.u64 %0, t; }" : "=r"(a) : "l"(p));
    return a;
}
__device__ __forceinline__ void ldsm4(uint32_t* r, uint32_t addr) {
    asm volatile("ldmatrix.sync.aligned.m8n8.x4.shared.b16 {%0,%1,%2,%3}, [%4];"
        : "=r"(r[0]), "=r"(r[1]), "=r"(r[2]), "=r"(r[3]) : "r"(addr));
}
__device__ __forceinline__ void mma_s8(int* d, const uint32_t* a, uint32_t b0, uint32_t b1) {
    asm volatile("mma.sync.aligned.m16n8k32.row.col.s32.s8.s8.s32 "
        "{%0,%1,%2,%3}, {%4,%5,%6,%7}, {%8,%9}, {%0,%1,%2,%3};"
        : "+r"(d[0]), "+r"(d[1]), "+r"(d[2]), "+r"(d[3])
        : "r"(a[0]), "r"(a[1]), "r"(a[2]), "r"(a[3]), "r"(b0), "r"(b1));
}

// ---------------------------------------------------------------------------
// Pre-pass: NCHW fp32 -> 3 NHWC s8 digit planes. v = lrint(x*2^18),
// v = d1*16384 + d2*128 + d3 exactly, digits in [-95,95].
// ---------------------------------------------------------------------------
__global__ __launch_bounds__(256)
void split_kernel(const float* __restrict__ x)
{
    __shared__ float sm[32 * 33];
    const int t = threadIdx.x, w0 = blockIdx.x * 32, h = blockIdx.y, n = blockIdx.z;
    {
        int c = t >> 3, j = t & 7;
        float4 v = *(const float4*)(x + (((size_t)(n * 32 + c) * 224 + h) * 224 + w0 + j * 4));
        sm[(j*4+0)*33+c] = v.x; sm[(j*4+1)*33+c] = v.y;
        sm[(j*4+2)*33+c] = v.z; sm[(j*4+3)*33+c] = v.w;
    }
    __syncthreads();
    const int ww = t >> 3, jj = t & 7;
    const size_t ob = (((size_t)((n * 224 + h) * 224) + (w0 + ww)) * 32 + jj * 4);
    uint32_t u1 = 0, u2 = 0, u3 = 0;
#pragma unroll
    for (int i = 0; i < 4; i++) {
        float v0 = sm[ww * 33 + jj * 4 + i];
        int v = __float2int_rn(v0 * 262144.0f);        // 2^18
        int d3 = ((v + 64) & 127) - 64;  v = (v - d3) >> 7;
        int d2 = ((v + 64) & 127) - 64;  v = (v - d2) >> 7;
        int d1 = v;                                    // |d1| <= 95
        u1 |= ((uint32_t)(d1 & 0xFF)) << (8 * i);
        u2 |= ((uint32_t)(d2 & 0xFF)) << (8 * i);
        u3 |= ((uint32_t)(d3 & 0xFF)) << (8 * i);
    }
    *(uint32_t*)(g_d1 + ob) = u1;
    *(uint32_t*)(g_d2 + ob) = u2;
    *(uint32_t*)(g_d3 + ob) = u3;
}

// ---------------------------------------------------------------------------
// Conv: IMMA (mma.sync m16n8k32 s8s8s32) implicit GEMM, exact arithmetic.
// CTA = (n, 4h x 32w): M=128 positions, N=32 co. Warp i = 16 consecutive w
// at h row (i>>1), cols (i&1)*16. Per tap: B 2 ldsm4, per digit plane:
// A 1 ldsm4 + 4 mma. Y = 16384*Y1 + 128*Y2 + Y3 (int32 exact), y = Y*2^-18.
// A smem: 3 planes x 204 halo pos x 32B, XOR-16B swizzle (conflict-free ldsm).
// B smem: 9 taps x 32 o x 32B (s8 ±1), same swizzle.
// ---------------------------------------------------------------------------
#define A_COMP_B 6528      // 204*32
#define A_TOT_B  19584     // 3*6528
#define B_TOT_B  9216      // 9*32*32
#define CONV_SMEM (A_TOT_B + B_TOT_B)   // 28800

__global__ __launch_bounds__(256, 2)
void conv_kernel(const float* __restrict__ wgt, float* __restrict__ out)
{
    extern __shared__ unsigned char dsm[];
    unsigned char* Asm = dsm;
    unsigned char* Bsm = dsm + A_TOT_B;
    float* smt = (float*)dsm;            // alias after mainloop: 128 m x 36 f32
    __shared__ double sred[256];         // [which 0..1][part 0..3][o 0..31]

    const int tid = threadIdx.x;
    const int l = tid & 31, warp = tid >> 5;
    const int w0 = blockIdx.x * 32, h0 = blockIdx.y * 4, n = blockIdx.z;
    const uint32_t Abase = smem_u32(Asm), Bbase = smem_u32(Bsm);

    // ---- stage B: binarized weights as s8 ±1, [tap][o][32 ch], swizzled ----
    for (int i = tid; i < 576; i += 256) {
        int tap = i / 64, rem = i & 63, o = rem >> 1, c = rem & 1;
        uint32_t pk[4];
#pragma unroll
        for (int q = 0; q < 4; q++) {
            uint32_t wv = 0;
#pragma unroll
            for (int b = 0; b < 4; b++) {
                int ch = c * 16 + q * 4 + b;
                wv |= ((wgt[o * 288 + ch * 9 + tap] >= 0.0f) ? 0x01u : 0xFFu) << (8 * b);
            }
            pk[q] = wv;
        }
        *(uint4*)(Bsm + (tap * 32 + o) * 32 + ((c ^ ((o >> 2) & 1)) << 4)) =
            make_uint4(pk[0], pk[1], pk[2], pk[3]);
    }
    // ---- stage A: 3 digit planes, 204 halo positions x 32B each ----
    for (int i = tid; i < 1224; i += 256) {
        int comp = i / 408, rem = i - comp * 408, pos = rem >> 1, c = rem & 1;
        int hr = pos / 34, hc = pos - hr * 34;
        int gh = h0 + hr - 1, gw = w0 + hc - 1;
        uint4 v = make_uint4(0u, 0u, 0u, 0u);
        if (gh >= 0 && gh < HH && gw >= 0 && gw < WW) {
            const signed char* pl = (comp == 0) ? g_d1 : ((comp == 1) ? g_d2 : g_d3);
            v = *(const uint4*)(pl + (size_t)((n * 224 + gh) * 224 + gw) * 32 + c * 16);
        }
        *(uint4*)(Asm + comp * A_COMP_B + pos * 32 + ((c ^ ((pos >> 2) & 1)) << 4)) = v;
    }
    __syncthreads();

    // ---- mainloop ----
    const int hh_w = warp >> 1, ww0 = (warp & 1) << 4;
    const int row_r = (l & 7) + ((l >> 3) & 1) * 8;   // ldsm row within 16
    const int cc = l >> 4;                            // 16B chunk select

    int acc1[16], acc2[16], acc3[16];
#pragma unroll
    for (int i = 0; i < 16; i++) { acc1[i] = 0; acc2[i] = 0; acc3[i] = 0; }

#pragma unroll
    for (int tap = 0; tap < 9; tap++) {
        const int dy = tap / 3, dx = tap - (tap / 3) * 3;
        uint32_t Bf[8];
#pragma unroll
        for (int nh = 0; nh < 2; nh++) {
            int o = nh * 16 + row_r;
            ldsm4(Bf + nh * 4, Bbase + (uint32_t)((tap * 32 + o) * 32 + ((cc ^ ((o >> 2) & 1)) << 4)));
        }
        const int p = (hh_w + dy) * 34 + (ww0 + dx) + row_r;
        const uint32_t aswz = (uint32_t)(p * 32 + ((cc ^ ((p >> 2) & 1)) << 4));
#pragma unroll
        for (int comp = 0; comp < 3; comp++) {
            uint32_t Af[4];
            ldsm4(Af, Abase + (uint32_t)(comp * A_COMP_B) + aswz);
            int* acc = (comp == 0) ? acc1 : ((comp == 1) ? acc2 : acc3);
#pragma unroll
            for (int ni = 0; ni < 4; ni++)
                mma_s8(acc + ni * 4, Af,
                       Bf[(ni >> 1) * 4 + (ni & 1)],
                       Bf[(ni >> 1) * 4 + 2 + (ni & 1)]);
        }
    }
    __syncthreads();   // smem reads done; smt aliases Asm/Bsm

    // ---- combine digits exactly, transpose to smt[m][o] ----
    {
        const int g = l >> 2, t4 = l & 3;
        const float invK = 3.814697265625e-06f;   // 2^-18
#pragma unroll
        for (int ni = 0; ni < 4; ni++) {
            const int o0 = ni * 8 + 2 * t4;
            const int m_lo = warp * 16 + g, m_hi = m_lo + 8;
#pragma unroll
            for (int e = 0; e < 4; e++) {
                int Yt = 16384 * acc1[ni*4+e] + 128 * acc2[ni*4+e] + acc3[ni*4+e];
                float y = (float)Yt * invK;
                int m = (e < 2) ? m_lo : m_hi;
                smt[m * 36 + o0 + (e & 1)] = y;
            }
        }
    }
    __syncthreads();

    // ---- BN stats: f32 inner over 32 m, double outer (fixed order) ----
    if (tid < 128) {
        const int o = tid & 31, part = tid >> 5;
        float s = 0.0f, q = 0.0f;
#pragma unroll
        for (int m = part * 32; m < part * 32 + 32; m++) {
            float v = smt[m * 36 + o];
            s += v;
            q = fmaf(v, v, q);
        }
        sred[part * 32 + o]       = (double)s;
        sred[128 + part * 32 + o] = (double)q;
    }
    // ---- store: m = tid>>1, 16 channels per thread, coalesced per warp ----
    {
        const int m = tid >> 1, half = tid & 1;
        const int hh2 = m >> 5, wwm = m & 31;
        float* ob = out + ((size_t)n * 32 + half * 16) * 224 * 224
                        + (size_t)(h0 + hh2) * 224 + w0 + wwm;
#pragma unroll
        for (int j = 0; j < 16; j++)
            ob[(size_t)j * 224 * 224] = smt[m * 36 + half * 16 + j];
    }
    __syncthreads();

    const int bflat = blockIdx.x + GX * (blockIdx.y + GYT * blockIdx.z);
    if (tid < 64) {
        const int cch = tid & 31, which = tid >> 5;
        double a = 0.0;
#pragma unroll
        for (int part = 0; part < 4; part++)
            a += sred[which * 128 + part * 32 + cch];
        g_part[bflat * 64 + which * 32 + cch] = a;
    }
}

// ---------------------------------------------------------------------------
__global__ void reduce_kernel(const float* __restrict__ gamma,
                              const float* __restrict__ beta)
{
    const int c = blockIdx.x, t = threadIdx.x;   // 32 blocks x 256 threads
    __shared__ double sh[512];
    double s = 0.0, q = 0.0;
    for (int b = t; b < NBLK; b += 256) {
        s += g_part[b * 64 + c];
        q += g_part[b * 64 + 32 + c];
    }
    sh[t] = s; sh[256 + t] = q;
    __syncthreads();
    for (int step = 128; step > 0; step >>= 1) {
        if (t < step) { sh[t] += sh[t + step]; sh[256 + t] += sh[256 + t + step]; }
        __syncthreads();
    }
    if (t == 0) {
        const double Nc = (double)NB * HH * WW;
        double mean = sh[0] / Nc;
        double var  = sh[256] / Nc - mean * mean;
        double inv  = 1.0 / sqrt(var + 1e-5);
        double sc   = (double)gamma[c] * inv;
        g_scale[c] = (float)sc;
        g_bias[c]  = (float)((double)beta[c] - mean * sc);
    }
}

// ---------------------------------------------------------------------------
__device__ __forceinline__ float qclamp(float v, float sc, float bi)
{
    float y = fmaf(v, sc, bi);
    y = fminf(fmaxf(y, -1.0f), 1.0f);
    return rintf(y * 2.0f) * 0.5f;
}

__global__ void finalize_kernel(float4* __restrict__ out)
{
    const unsigned i = blockIdx.x * 256u + threadIdx.x;   // < 6422528
    const int c = (int)((i / 12544u) & 31u);
    const float sc = g_scale[c], bi = g_bias[c];
    float4 v = out[i];
    v.x = qclamp(v.x, sc, bi); v.y = qclamp(v.y, sc, bi);
    v.z = qclamp(v.z, sc, bi); v.w = qclamp(v.w, sc, bi);
    out[i] = v;
}

// ---------------------------------------------------------------------------
extern "C" void kernel_launch(void* const* d_in, const int* in_sizes, int n_in,
                              void* d_out, int out_size)
{
    const float* x     = (const float*)d_in[0];
    const float* wgt   = (const float*)d_in[1];
    const float* gamma = (const float*)d_in[2];
    const float* beta  = (const float*)d_in[3];
    float* out = (float*)d_out;

    cudaFuncSetAttribute(conv_kernel, cudaFuncAttributeMaxDynamicSharedMemorySize, CONV_SMEM);

    split_kernel<<<dim3(7, 224, NB), 256>>>(x);
    conv_kernel<<<dim3(GX, GYT, NB), 256, CONV_SMEM>>>(wgt, out);
    reduce_kernel<<<32, 256>>>(gamma, beta);
    finalize_kernel<<<25088, 256>>>((float4*)d_out);
}